// round 3
// baseline (speedup 1.0000x reference)
#include <cuda_runtime.h>
#include <cstdint>

#define NPv 50000
#define NAv 50000
#define Dv  128

// ---------------- scratch (static device globals; no allocation) -------------
__device__ float g_agg1[(size_t)NPv * Dv];
__device__ float g_agg2[(size_t)NPv * Dv];
__device__ float g_agg3[(size_t)NAv * Dv];
__device__ float g_z1[(size_t)NPv * Dv];
__device__ float g_z2[(size_t)NPv * Dv];
__device__ float g_z3[(size_t)NAv * Dv];
__device__ float g_deg[6 * 50000];
__device__ float g_stats[7 * 128];
__device__ float g_wsum[2];
__device__ float g_beta[2];
__device__ float g_scale_p[128], g_shift_p[128];
__device__ float g_scale_a[128], g_shift_a[128];

// ---------------- f32x2 helpers ----------------
__device__ __forceinline__ uint64_t pack2(float x, float y) {
    uint64_t r;
    asm("mov.b64 %0, {%1, %2};" : "=l"(r) : "f"(x), "f"(y));
    return r;
}
__device__ __forceinline__ void unpack2(uint64_t v, float& x, float& y) {
    asm("mov.b64 {%0, %1}, %2;" : "=f"(x), "=f"(y) : "l"(v));
}
__device__ __forceinline__ uint64_t ffma2(uint64_t a, uint64_t b, uint64_t c) {
    uint64_t d;
    asm("fma.rn.f32x2 %0, %1, %2, %3;" : "=l"(d) : "l"(a), "l"(b), "l"(c));
    return d;
}
__device__ __forceinline__ float pairsum(uint64_t v) {
    float x, y;
    unpack2(v, x, y);
    return x + y;
}

// ---------------- zero scratch ----------------
__global__ void zero_kernel() {
    size_t i = (size_t)blockIdx.x * blockDim.x + threadIdx.x;
    size_t n1 = (size_t)NPv * Dv;
    if (i < n1) { g_agg1[i] = 0.f; g_agg2[i] = 0.f; g_agg3[i] = 0.f; }
    if (i < 6 * 50000) g_deg[i] = 0.f;
    if (i < 7 * 128) g_stats[i] = 0.f;
    if (i < 2) g_wsum[i] = 0.f;
}

// ---------------- degrees ----------------
__global__ void degree_kernel(const int* __restrict__ s1, const int* __restrict__ d1,
                              const int* __restrict__ s2, const int* __restrict__ d2,
                              const int* __restrict__ s3, const int* __restrict__ d3,
                              int nE) {
    int i = blockIdx.x * blockDim.x + threadIdx.x;
    if (i >= nE) return;
    atomicAdd(&g_deg[0 * 50000 + s1[i]], 1.0f);
    atomicAdd(&g_deg[1 * 50000 + d1[i]], 1.0f);
    atomicAdd(&g_deg[2 * 50000 + s2[i]], 1.0f);
    atomicAdd(&g_deg[3 * 50000 + d2[i]], 1.0f);
    atomicAdd(&g_deg[4 * 50000 + s3[i]], 1.0f);
    atomicAdd(&g_deg[5 * 50000 + d3[i]], 1.0f);
}

__global__ void rsqrt_deg_kernel(int n) {
    int i = blockIdx.x * blockDim.x + threadIdx.x;
    if (i < n) g_deg[i] = rsqrtf(fmaxf(g_deg[i], 1.0f));
}

// ---------------- scatter: 4 edges per warp for MLP (at LTS cap) -------------
__global__ __launch_bounds__(256) void scatter_kernel(
    const float* __restrict__ H, const int* __restrict__ src, const int* __restrict__ dst,
    const float* __restrict__ rs_out, float* __restrict__ agg, int nE) {
    int warp = (blockIdx.x * blockDim.x + threadIdx.x) >> 5;
    int lane = threadIdx.x & 31;
    int e0 = warp << 2;
    if (e0 >= nE) return;

    int s[4], d[4];
#pragma unroll
    for (int i = 0; i < 4; i++) {
        int e = min(e0 + i, nE - 1);
        s[i] = __ldg(src + e);
        d[i] = __ldg(dst + e);
    }
    float sc[4];
#pragma unroll
    for (int i = 0; i < 4; i++) sc[i] = __ldg(rs_out + s[i]);
    float4 v[4];
#pragma unroll
    for (int i = 0; i < 4; i++)
        v[i] = *((const float4*)(H + (size_t)s[i] * Dv) + lane);

    int n = min(4, nE - e0);
#pragma unroll
    for (int i = 0; i < 4; i++) {
        if (i < n) {
            float4 u = v[i];
            float c = sc[i];
            u.x *= c; u.y *= c; u.z *= c; u.w *= c;
            float* p = agg + (size_t)d[i] * Dv + lane * 4;
            asm volatile("red.global.add.v4.f32 [%0], {%1,%2,%3,%4};"
                         :: "l"(p), "f"(u.x), "f"(u.y), "f"(u.z), "f"(u.w) : "memory");
        }
    }
}

// ---------------- GEMM (K-paired f32x2): C = (A @ W) * rs[row] ---------------
// 256 threads, 64 rows x 64 cols, thread tile 4x4, k step 4 (= 2 k-pairs)
__global__ __launch_bounds__(256) void gemm_rowscale(
    const float* __restrict__ A, const float* __restrict__ W,
    const float* __restrict__ rs, float* __restrict__ C, int M) {
    __shared__ float Ws[128][64];
    const int tid = threadIdx.x;
    const int rowBase = blockIdx.x * 64;
    const int colBase = blockIdx.y * 64;

    for (int i = tid; i < 128 * 16; i += 256) {
        int k = i >> 4, c4 = (i & 15) << 2;
        *(float4*)&Ws[k][c4] = *(const float4*)(W + k * 128 + colBase + c4);
    }
    __syncthreads();

    const int tx = tid & 15, ty = tid >> 4;
    const int col = tx << 2;

    int rr0 = min(rowBase + ty * 4 + 0, M - 1);
    int rr1 = min(rowBase + ty * 4 + 1, M - 1);
    int rr2 = min(rowBase + ty * 4 + 2, M - 1);
    int rr3 = min(rowBase + ty * 4 + 3, M - 1);
    const ulonglong2* A0 = (const ulonglong2*)(A + (size_t)rr0 * 128);
    const ulonglong2* A1 = (const ulonglong2*)(A + (size_t)rr1 * 128);
    const ulonglong2* A2 = (const ulonglong2*)(A + (size_t)rr2 * 128);
    const ulonglong2* A3 = (const ulonglong2*)(A + (size_t)rr3 * 128);

    uint64_t acc[4][4];
#pragma unroll
    for (int r = 0; r < 4; r++)
#pragma unroll
        for (int j = 0; j < 4; j++) acc[r][j] = 0ull;

#pragma unroll 4
    for (int k4 = 0; k4 < 32; k4++) {
        // A: k-pairs come free from the 128-bit load
        ulonglong2 av0 = A0[k4], av1 = A1[k4], av2 = A2[k4], av3 = A3[k4];
        // W: 4 k-rows, pack k-pairs per column (8 packs, ALU pipe, hidden)
        float4 w0 = *(const float4*)&Ws[k4 * 4 + 0][col];
        float4 w1 = *(const float4*)&Ws[k4 * 4 + 1][col];
        float4 w2 = *(const float4*)&Ws[k4 * 4 + 2][col];
        float4 w3 = *(const float4*)&Ws[k4 * 4 + 3][col];
        uint64_t wp01[4], wp23[4];
        wp01[0] = pack2(w0.x, w1.x); wp01[1] = pack2(w0.y, w1.y);
        wp01[2] = pack2(w0.z, w1.z); wp01[3] = pack2(w0.w, w1.w);
        wp23[0] = pack2(w2.x, w3.x); wp23[1] = pack2(w2.y, w3.y);
        wp23[2] = pack2(w2.z, w3.z); wp23[3] = pack2(w2.w, w3.w);
#pragma unroll
        for (int j = 0; j < 4; j++) {
            acc[0][j] = ffma2(av0.x, wp01[j], acc[0][j]);
            acc[1][j] = ffma2(av1.x, wp01[j], acc[1][j]);
            acc[2][j] = ffma2(av2.x, wp01[j], acc[2][j]);
            acc[3][j] = ffma2(av3.x, wp01[j], acc[3][j]);
            acc[0][j] = ffma2(av0.y, wp23[j], acc[0][j]);
            acc[1][j] = ffma2(av1.y, wp23[j], acc[1][j]);
            acc[2][j] = ffma2(av2.y, wp23[j], acc[2][j]);
            acc[3][j] = ffma2(av3.y, wp23[j], acc[3][j]);
        }
    }
#pragma unroll
    for (int r = 0; r < 4; r++) {
        int row = rowBase + ty * 4 + r;
        if (row < M) {
            float s = rs[row];
            float4 o;
            o.x = pairsum(acc[r][0]) * s;
            o.y = pairsum(acc[r][1]) * s;
            o.z = pairsum(acc[r][2]) * s;
            o.w = pairsum(acc[r][3]) * s;
            *(float4*)(C + (size_t)row * 128 + colBase + col) = o;
        }
    }
}

// ---------------- attention score (K-paired f32x2 GEMM + tanh dot) -----------
__global__ __launch_bounds__(256) void att_score_kernel(
    const float* __restrict__ Z, const float* __restrict__ attW,
    const float* __restrict__ attb, const float* __restrict__ attq,
    float* __restrict__ wsum, int M) {
    __shared__ float Ws[128][64];
    __shared__ float ssum;
    const int tid = threadIdx.x;
    const int rowBase = blockIdx.x * 64;
    const int colBase = blockIdx.y * 64;
    if (tid == 0) ssum = 0.f;

    for (int i = tid; i < 128 * 16; i += 256) {
        int k = i >> 4, c4 = (i & 15) << 2;
        *(float4*)&Ws[k][c4] = *(const float4*)(attW + k * 128 + colBase + c4);
    }
    __syncthreads();

    const int tx = tid & 15, ty = tid >> 4;
    const int col = tx << 2;

    int rr0 = min(rowBase + ty * 4 + 0, M - 1);
    int rr1 = min(rowBase + ty * 4 + 1, M - 1);
    int rr2 = min(rowBase + ty * 4 + 2, M - 1);
    int rr3 = min(rowBase + ty * 4 + 3, M - 1);
    const ulonglong2* A0 = (const ulonglong2*)(Z + (size_t)rr0 * 128);
    const ulonglong2* A1 = (const ulonglong2*)(Z + (size_t)rr1 * 128);
    const ulonglong2* A2 = (const ulonglong2*)(Z + (size_t)rr2 * 128);
    const ulonglong2* A3 = (const ulonglong2*)(Z + (size_t)rr3 * 128);

    uint64_t acc[4][4];
#pragma unroll
    for (int r = 0; r < 4; r++)
#pragma unroll
        for (int j = 0; j < 4; j++) acc[r][j] = 0ull;

#pragma unroll 4
    for (int k4 = 0; k4 < 32; k4++) {
        ulonglong2 av0 = A0[k4], av1 = A1[k4], av2 = A2[k4], av3 = A3[k4];
        float4 w0 = *(const float4*)&Ws[k4 * 4 + 0][col];
        float4 w1 = *(const float4*)&Ws[k4 * 4 + 1][col];
        float4 w2 = *(const float4*)&Ws[k4 * 4 + 2][col];
        float4 w3 = *(const float4*)&Ws[k4 * 4 + 3][col];
        uint64_t wp01[4], wp23[4];
        wp01[0] = pack2(w0.x, w1.x); wp01[1] = pack2(w0.y, w1.y);
        wp01[2] = pack2(w0.z, w1.z); wp01[3] = pack2(w0.w, w1.w);
        wp23[0] = pack2(w2.x, w3.x); wp23[1] = pack2(w2.y, w3.y);
        wp23[2] = pack2(w2.z, w3.z); wp23[3] = pack2(w2.w, w3.w);
#pragma unroll
        for (int j = 0; j < 4; j++) {
            acc[0][j] = ffma2(av0.x, wp01[j], acc[0][j]);
            acc[1][j] = ffma2(av1.x, wp01[j], acc[1][j]);
            acc[2][j] = ffma2(av2.x, wp01[j], acc[2][j]);
            acc[3][j] = ffma2(av3.x, wp01[j], acc[3][j]);
            acc[0][j] = ffma2(av0.y, wp23[j], acc[0][j]);
            acc[1][j] = ffma2(av1.y, wp23[j], acc[1][j]);
            acc[2][j] = ffma2(av2.y, wp23[j], acc[2][j]);
            acc[3][j] = ffma2(av3.y, wp23[j], acc[3][j]);
        }
    }

    float bq_b[4], bq_q[4];
#pragma unroll
    for (int j = 0; j < 4; j++) {
        bq_b[j] = attb[colBase + col + j];
        bq_q[j] = attq[colBase + col + j];
    }
    float p = 0.f;
#pragma unroll
    for (int r = 0; r < 4; r++) {
        int row = rowBase + ty * 4 + r;
        if (row < M) {
#pragma unroll
            for (int j = 0; j < 4; j++)
                p += tanhf(pairsum(acc[r][j]) + bq_b[j]) * bq_q[j];
        }
    }
    p += __shfl_down_sync(0xffffffffu, p, 8, 16);
    p += __shfl_down_sync(0xffffffffu, p, 4, 16);
    p += __shfl_down_sync(0xffffffffu, p, 2, 16);
    p += __shfl_down_sync(0xffffffffu, p, 1, 16);
    if (tx == 0) atomicAdd(&ssum, p);
    __syncthreads();
    if (tid == 0) atomicAdd(wsum, ssum);
}

// ---------------- column moments ----------------
__global__ __launch_bounds__(128) void stats_paper_kernel(
    const float* __restrict__ z1, const float* __restrict__ z2, int M) {
    int c = threadIdx.x;
    int r0 = blockIdx.x * 256;
    int r1 = min(r0 + 256, M);
    float s1 = 0.f, s2 = 0.f, q1 = 0.f, q2 = 0.f, cx = 0.f;
    for (int r = r0; r < r1; r++) {
        float v1 = z1[(size_t)r * 128 + c];
        float v2 = z2[(size_t)r * 128 + c];
        s1 += v1; s2 += v2; q1 += v1 * v1; q2 += v2 * v2; cx += v1 * v2;
    }
    atomicAdd(&g_stats[0 * 128 + c], s1);
    atomicAdd(&g_stats[1 * 128 + c], s2);
    atomicAdd(&g_stats[2 * 128 + c], q1);
    atomicAdd(&g_stats[3 * 128 + c], q2);
    atomicAdd(&g_stats[4 * 128 + c], cx);
}

__global__ __launch_bounds__(128) void stats_author_kernel(const float* __restrict__ z3, int M) {
    int c = threadIdx.x;
    int r0 = blockIdx.x * 256;
    int r1 = min(r0 + 256, M);
    float s3 = 0.f, q3 = 0.f;
    for (int r = r0; r < r1; r++) {
        float v = z3[(size_t)r * 128 + c];
        s3 += v; q3 += v * v;
    }
    atomicAdd(&g_stats[5 * 128 + c], s3);
    atomicAdd(&g_stats[6 * 128 + c], q3);
}

// ---------------- finalize: beta softmax + BN affine params ----------------
__global__ void finalize_kernel(const float* __restrict__ gamma, const float* __restrict__ betaBN,
                                int MP, int MA) {
    int j = threadIdx.x;
    float w1 = g_wsum[0] / (float)MP;
    float w2 = g_wsum[1] / (float)MP;
    float m = fmaxf(w1, w2);
    float e1 = expf(w1 - m), e2 = expf(w2 - m);
    float b1 = e1 / (e1 + e2), b2 = e2 / (e1 + e2);
    if (j == 0) { g_beta[0] = b1; g_beta[1] = b2; }

    float S1 = g_stats[0 * 128 + j], S2 = g_stats[1 * 128 + j];
    float Q1 = g_stats[2 * 128 + j], Q2 = g_stats[3 * 128 + j];
    float CX = g_stats[4 * 128 + j];
    float S3 = g_stats[5 * 128 + j], Q3 = g_stats[6 * 128 + j];

    float invMP = 1.0f / (float)MP;
    float mu = (b1 * S1 + b2 * S2) * invMP;
    float ex2 = (b1 * b1 * Q1 + 2.f * b1 * b2 * CX + b2 * b2 * Q2) * invMP;
    float var = ex2 - mu * mu;
    float sc = gamma[j] * rsqrtf(var + 1e-5f);
    g_scale_p[j] = sc;
    g_shift_p[j] = betaBN[j] - mu * sc;

    float invMA = 1.0f / (float)MA;
    float mua = S3 * invMA;
    float vara = Q3 * invMA - mua * mua;
    float sca = gamma[j] * rsqrtf(vara + 1e-5f);
    g_scale_a[j] = sca;
    g_shift_a[j] = betaBN[j] - mua * sca;
}

// ---------------- combine + BN + row L2 normalize ----------------
__global__ __launch_bounds__(256) void out_paper_kernel(
    const float* __restrict__ z1, const float* __restrict__ z2,
    float* __restrict__ out, int M) {
    int gt = blockIdx.x * blockDim.x + threadIdx.x;
    int row = gt >> 5, lane = gt & 31;
    if (row >= M) return;
    float b1 = g_beta[0], b2 = g_beta[1];
    float4 v1 = *((const float4*)(z1 + (size_t)row * 128) + lane);
    float4 v2 = *((const float4*)(z2 + (size_t)row * 128) + lane);
    float4 sc = *(const float4*)&g_scale_p[lane * 4];
    float4 sh = *(const float4*)&g_shift_p[lane * 4];
    float4 y;
    y.x = (b1 * v1.x + b2 * v2.x) * sc.x + sh.x;
    y.y = (b1 * v1.y + b2 * v2.y) * sc.y + sh.y;
    y.z = (b1 * v1.z + b2 * v2.z) * sc.z + sh.z;
    y.w = (b1 * v1.w + b2 * v2.w) * sc.w + sh.w;
    float ss = y.x * y.x + y.y * y.y + y.z * y.z + y.w * y.w;
#pragma unroll
    for (int o = 16; o > 0; o >>= 1) ss += __shfl_xor_sync(0xffffffffu, ss, o);
    float inv = rsqrtf(ss + 1e-12f);
    float4 o4 = make_float4(y.x * inv, y.y * inv, y.z * inv, y.w * inv);
    *((float4*)(out + (size_t)row * 128) + lane) = o4;
}

__global__ __launch_bounds__(256) void out_author_kernel(
    const float* __restrict__ z3, float* __restrict__ out, int M) {
    int gt = blockIdx.x * blockDim.x + threadIdx.x;
    int row = gt >> 5, lane = gt & 31;
    if (row >= M) return;
    float4 v = *((const float4*)(z3 + (size_t)row * 128) + lane);
    float4 sc = *(const float4*)&g_scale_a[lane * 4];
    float4 sh = *(const float4*)&g_shift_a[lane * 4];
    float4 y;
    y.x = v.x * sc.x + sh.x;
    y.y = v.y * sc.y + sh.y;
    y.z = v.z * sc.z + sh.z;
    y.w = v.w * sc.w + sh.w;
    float ss = y.x * y.x + y.y * y.y + y.z * y.z + y.w * y.w;
#pragma unroll
    for (int o = 16; o > 0; o >>= 1) ss += __shfl_xor_sync(0xffffffffu, ss, o);
    float inv = rsqrtf(ss + 1e-12f);
    float4 o4 = make_float4(y.x * inv, y.y * inv, y.z * inv, y.w * inv);
    *((float4*)(out + (size_t)row * 128) + lane) = o4;
}

// ---------------- launch ----------------
extern "C" void kernel_launch(void* const* d_in, const int* in_sizes, int n_in,
                              void* d_out, int out_size) {
    const float* h_paper  = (const float*)d_in[0];
    const float* h_author = (const float*)d_in[1];
    const float* W1   = (const float*)d_in[2];
    const float* W2   = (const float*)d_in[3];
    const float* W3   = (const float*)d_in[4];
    const float* attW = (const float*)d_in[5];
    const float* attb = (const float*)d_in[6];
    const float* attq = (const float*)d_in[7];
    const float* gamma  = (const float*)d_in[8];
    const float* betaBN = (const float*)d_in[9];
    const int* s1 = (const int*)d_in[10];
    const int* d1 = (const int*)d_in[11];
    const int* s2 = (const int*)d_in[12];
    const int* d2 = (const int*)d_in[13];
    const int* s3 = (const int*)d_in[14];
    const int* d3 = (const int*)d_in[15];
    float* out = (float*)d_out;

    const int MP = in_sizes[0] / Dv;
    const int MA = in_sizes[1] / Dv;
    const int E  = in_sizes[10];

    float *agg1, *agg2, *agg3, *z1, *z2, *z3, *deg, *wsum;
    cudaGetSymbolAddress((void**)&agg1, g_agg1);
    cudaGetSymbolAddress((void**)&agg2, g_agg2);
    cudaGetSymbolAddress((void**)&agg3, g_agg3);
    cudaGetSymbolAddress((void**)&z1, g_z1);
    cudaGetSymbolAddress((void**)&z2, g_z2);
    cudaGetSymbolAddress((void**)&z3, g_z3);
    cudaGetSymbolAddress((void**)&deg, g_deg);
    cudaGetSymbolAddress((void**)&wsum, g_wsum);

    {
        size_t n = (size_t)MP * Dv;
        int blocks = (int)((n + 255) / 256);
        zero_kernel<<<blocks, 256>>>();
    }
    degree_kernel<<<(E + 255) / 256, 256>>>(s1, d1, s2, d2, s3, d3, E);
    rsqrt_deg_kernel<<<(6 * 50000 + 255) / 256, 256>>>(6 * 50000);

    {
        int warps = (E + 3) / 4;
        int blocks = (warps * 32 + 255) / 256;
        scatter_kernel<<<blocks, 256>>>(h_author, s1, d1, deg + 0 * 50000, agg1, E);
        scatter_kernel<<<blocks, 256>>>(h_paper,  s2, d2, deg + 2 * 50000, agg2, E);
        scatter_kernel<<<blocks, 256>>>(h_author, s3, d3, deg + 4 * 50000, agg3, E);
    }

    {
        dim3 gP((MP + 63) / 64, 2), gA((MA + 63) / 64, 2);
        gemm_rowscale<<<gP, 256>>>(agg1, W1, deg + 1 * 50000, z1, MP);
        gemm_rowscale<<<gP, 256>>>(agg2, W2, deg + 3 * 50000, z2, MP);
        gemm_rowscale<<<gA, 256>>>(agg3, W3, deg + 5 * 50000, z3, MA);
    }

    {
        dim3 gP((MP + 63) / 64, 2);
        att_score_kernel<<<gP, 256>>>(z1, attW, attb, attq, wsum + 0, MP);
        att_score_kernel<<<gP, 256>>>(z2, attW, attb, attq, wsum + 1, MP);
    }

    stats_paper_kernel<<<(MP + 255) / 256, 128>>>(z1, z2, MP);
    stats_author_kernel<<<(MA + 255) / 256, 128>>>(z3, MA);

    finalize_kernel<<<1, 128>>>(gamma, betaBN, MP, MA);

    out_paper_kernel<<<(MP * 32 + 255) / 256, 256>>>(z1, z2, out, MP);
    out_author_kernel<<<(MA * 32 + 255) / 256, 256>>>(z3, out + (size_t)MP * Dv, MA);
}

// round 4
// speedup vs baseline: 1.5072x; 1.5072x over previous
#include <cuda_runtime.h>
#include <cstdint>

#define NPv 50000
#define NAv 50000
#define Dv  128

// ---------------- scratch (static device globals; no allocation) -------------
__device__ float g_agg1[(size_t)NPv * Dv];
__device__ float g_agg2[(size_t)NPv * Dv];
__device__ float g_agg3[(size_t)NAv * Dv];
__device__ float g_z1[(size_t)NPv * Dv];
__device__ float g_z2[(size_t)NPv * Dv];
__device__ float g_z3[(size_t)NAv * Dv];
__device__ float g_deg[6 * 50000];
__device__ float g_stats[7 * 128];
__device__ float g_wsum[2];
__device__ float g_beta[2];
__device__ float g_scale_p[128], g_shift_p[128];
__device__ float g_scale_a[128], g_shift_a[128];

// ---------------- tf32 helpers ----------------
__device__ __forceinline__ uint32_t cvt_tf32(float x) {
    uint32_t r;
    asm("cvt.rna.tf32.f32 %0, %1;" : "=r"(r) : "f"(x));
    return r;
}
__device__ __forceinline__ void mma_tf32(float4& d, const uint32_t a[4],
                                         uint32_t b0, uint32_t b1) {
    asm volatile(
        "mma.sync.aligned.m16n8k8.row.col.f32.tf32.tf32.f32 "
        "{%0,%1,%2,%3},{%4,%5,%6,%7},{%8,%9},{%0,%1,%2,%3};"
        : "+f"(d.x), "+f"(d.y), "+f"(d.z), "+f"(d.w)
        : "r"(a[0]), "r"(a[1]), "r"(a[2]), "r"(a[3]), "r"(b0), "r"(b1));
}

// ---------------- zero scratch ----------------
__global__ void zero_kernel() {
    size_t i = (size_t)blockIdx.x * blockDim.x + threadIdx.x;
    size_t n1 = (size_t)NPv * Dv;
    if (i < n1) { g_agg1[i] = 0.f; g_agg2[i] = 0.f; g_agg3[i] = 0.f; }
    if (i < 6 * 50000) g_deg[i] = 0.f;
    if (i < 7 * 128) g_stats[i] = 0.f;
    if (i < 2) g_wsum[i] = 0.f;
}

// ---------------- degrees ----------------
__global__ void degree_kernel(const int* __restrict__ s1, const int* __restrict__ d1,
                              const int* __restrict__ s2, const int* __restrict__ d2,
                              const int* __restrict__ s3, const int* __restrict__ d3,
                              int nE) {
    int i = blockIdx.x * blockDim.x + threadIdx.x;
    if (i >= nE) return;
    atomicAdd(&g_deg[0 * 50000 + s1[i]], 1.0f);
    atomicAdd(&g_deg[1 * 50000 + d1[i]], 1.0f);
    atomicAdd(&g_deg[2 * 50000 + s2[i]], 1.0f);
    atomicAdd(&g_deg[3 * 50000 + d2[i]], 1.0f);
    atomicAdd(&g_deg[4 * 50000 + s3[i]], 1.0f);
    atomicAdd(&g_deg[5 * 50000 + d3[i]], 1.0f);
}

__global__ void rsqrt_deg_kernel(int n) {
    int i = blockIdx.x * blockDim.x + threadIdx.x;
    if (i < n) g_deg[i] = rsqrtf(fmaxf(g_deg[i], 1.0f));
}

// ---------------- scatter: 4 edges per warp for MLP (at LTS cap) -------------
__global__ __launch_bounds__(256) void scatter_kernel(
    const float* __restrict__ H, const int* __restrict__ src, const int* __restrict__ dst,
    const float* __restrict__ rs_out, float* __restrict__ agg, int nE) {
    int warp = (blockIdx.x * blockDim.x + threadIdx.x) >> 5;
    int lane = threadIdx.x & 31;
    int e0 = warp << 2;
    if (e0 >= nE) return;

    int s[4], d[4];
#pragma unroll
    for (int i = 0; i < 4; i++) {
        int e = min(e0 + i, nE - 1);
        s[i] = __ldg(src + e);
        d[i] = __ldg(dst + e);
    }
    float sc[4];
#pragma unroll
    for (int i = 0; i < 4; i++) sc[i] = __ldg(rs_out + s[i]);
    float4 v[4];
#pragma unroll
    for (int i = 0; i < 4; i++)
        v[i] = *((const float4*)(H + (size_t)s[i] * Dv) + lane);

    int n = min(4, nE - e0);
#pragma unroll
    for (int i = 0; i < 4; i++) {
        if (i < n) {
            float4 u = v[i];
            float c = sc[i];
            u.x *= c; u.y *= c; u.z *= c; u.w *= c;
            float* p = agg + (size_t)d[i] * Dv + lane * 4;
            asm volatile("red.global.add.v4.f32 [%0], {%1,%2,%3,%4};"
                         :: "l"(p), "f"(u.x), "f"(u.y), "f"(u.z), "f"(u.w) : "memory");
        }
    }
}

// ---------------- TF32 tensor-core GEMM, MODE 0: C=(A@W)*rs, MODE 1: att -----
// block 256 thr = 8 warps (4m x 2n). Block tile 128x64, warp tile 32x32.
// K=128 chunked by 32 through smem. Strides: As 36 (A-frag banks = lane),
// Ws 72 (B-frag banks = 8*tig+grp, bijective).
template<int MODE>
__global__ __launch_bounds__(256) void gemm_tf32(
    const float* __restrict__ A, const float* __restrict__ W,
    const float* __restrict__ rs, float* __restrict__ C,
    const float* __restrict__ bb, const float* __restrict__ qq,
    float* __restrict__ wsum, int M) {
    __shared__ float As[128][36];
    __shared__ float Ws[32][72];

    const int tid = threadIdx.x;
    const int wid = tid >> 5, lane = tid & 31;
    const int grp = lane >> 2, tig = lane & 3;
    const int rowBase = blockIdx.x * 128;
    const int colBase = blockIdx.y * 64;
    const int rowOff = (wid & 3) * 32;
    const int colOff = (wid >> 2) * 32;

    float4 acc[2][4];
#pragma unroll
    for (int ms = 0; ms < 2; ms++)
#pragma unroll
        for (int ns = 0; ns < 4; ns++) acc[ms][ns] = make_float4(0.f, 0.f, 0.f, 0.f);

    for (int kc = 0; kc < 4; kc++) {
        // ---- load A chunk [128 rows][32 k] ----
#pragma unroll
        for (int j = 0; j < 4; j++) {
            int i = tid + 256 * j;            // 0..1023 float4 slots
            int r = i >> 3, c4 = (i & 7) << 2;
            int gr = min(rowBase + r, M - 1);
            float4 v = *(const float4*)(A + (size_t)gr * 128 + kc * 32 + c4);
            uint4 t;
            t.x = cvt_tf32(v.x); t.y = cvt_tf32(v.y);
            t.z = cvt_tf32(v.z); t.w = cvt_tf32(v.w);
            *(uint4*)&As[r][c4] = t;
        }
        // ---- load W chunk [32 k][64 n] ----
#pragma unroll
        for (int j = 0; j < 2; j++) {
            int i = tid + 256 * j;            // 0..511 float4 slots
            int k = i >> 4, c4 = (i & 15) << 2;
            float4 v = *(const float4*)(W + (size_t)(kc * 32 + k) * 128 + colBase + c4);
            uint4 t;
            t.x = cvt_tf32(v.x); t.y = cvt_tf32(v.y);
            t.z = cvt_tf32(v.z); t.w = cvt_tf32(v.w);
            *(uint4*)&Ws[k][c4] = t;
        }
        __syncthreads();

#pragma unroll
        for (int ks = 0; ks < 4; ks++) {
            int k0 = ks * 8;
            uint32_t a[2][4];
#pragma unroll
            for (int ms = 0; ms < 2; ms++) {
                int r = rowOff + ms * 16 + grp;
                a[ms][0] = __float_as_uint(As[r][k0 + tig]);
                a[ms][1] = __float_as_uint(As[r + 8][k0 + tig]);
                a[ms][2] = __float_as_uint(As[r][k0 + tig + 4]);
                a[ms][3] = __float_as_uint(As[r + 8][k0 + tig + 4]);
            }
#pragma unroll
            for (int ns = 0; ns < 4; ns++) {
                int cn = colOff + ns * 8 + grp;
                uint32_t b0 = __float_as_uint(Ws[k0 + tig][cn]);
                uint32_t b1 = __float_as_uint(Ws[k0 + tig + 4][cn]);
                mma_tf32(acc[0][ns], a[0], b0, b1);
                mma_tf32(acc[1][ns], a[1], b0, b1);
            }
        }
        __syncthreads();
    }

    if (MODE == 0) {
        // C[row] = acc * rs[row]
#pragma unroll
        for (int ms = 0; ms < 2; ms++) {
            int rA = rowBase + rowOff + ms * 16 + grp;
            int rB = rA + 8;
            float sA = (rA < M) ? rs[rA] : 0.f;
            float sB = (rB < M) ? rs[rB] : 0.f;
#pragma unroll
            for (int ns = 0; ns < 4; ns++) {
                int cC = colBase + colOff + ns * 8 + 2 * tig;
                if (rA < M) {
                    float2 o = make_float2(acc[ms][ns].x * sA, acc[ms][ns].y * sA);
                    *(float2*)(C + (size_t)rA * 128 + cC) = o;
                }
                if (rB < M) {
                    float2 o = make_float2(acc[ms][ns].z * sB, acc[ms][ns].w * sB);
                    *(float2*)(C + (size_t)rB * 128 + cC) = o;
                }
            }
        }
    } else {
        // attention: p = sum tanh(acc + b[col]) * q[col] over valid rows
        float p = 0.f;
#pragma unroll
        for (int ms = 0; ms < 2; ms++) {
            int rA = rowBase + rowOff + ms * 16 + grp;
            int rB = rA + 8;
#pragma unroll
            for (int ns = 0; ns < 4; ns++) {
                int cC = colBase + colOff + ns * 8 + 2 * tig;
                float b0v = __ldg(bb + cC), b1v = __ldg(bb + cC + 1);
                float q0v = __ldg(qq + cC), q1v = __ldg(qq + cC + 1);
                if (rA < M)
                    p += tanhf(acc[ms][ns].x + b0v) * q0v + tanhf(acc[ms][ns].y + b1v) * q1v;
                if (rB < M)
                    p += tanhf(acc[ms][ns].z + b0v) * q0v + tanhf(acc[ms][ns].w + b1v) * q1v;
            }
        }
#pragma unroll
        for (int o = 16; o > 0; o >>= 1) p += __shfl_xor_sync(0xffffffffu, p, o);
        if (lane == 0) atomicAdd(wsum, p);
    }
}

// ---------------- column moments ----------------
__global__ __launch_bounds__(128) void stats_paper_kernel(
    const float* __restrict__ z1, const float* __restrict__ z2, int M) {
    int c = threadIdx.x;
    int r0 = blockIdx.x * 256;
    int r1 = min(r0 + 256, M);
    float s1 = 0.f, s2 = 0.f, q1 = 0.f, q2 = 0.f, cx = 0.f;
    for (int r = r0; r < r1; r++) {
        float v1 = z1[(size_t)r * 128 + c];
        float v2 = z2[(size_t)r * 128 + c];
        s1 += v1; s2 += v2; q1 += v1 * v1; q2 += v2 * v2; cx += v1 * v2;
    }
    atomicAdd(&g_stats[0 * 128 + c], s1);
    atomicAdd(&g_stats[1 * 128 + c], s2);
    atomicAdd(&g_stats[2 * 128 + c], q1);
    atomicAdd(&g_stats[3 * 128 + c], q2);
    atomicAdd(&g_stats[4 * 128 + c], cx);
}

__global__ __launch_bounds__(128) void stats_author_kernel(const float* __restrict__ z3, int M) {
    int c = threadIdx.x;
    int r0 = blockIdx.x * 256;
    int r1 = min(r0 + 256, M);
    float s3 = 0.f, q3 = 0.f;
    for (int r = r0; r < r1; r++) {
        float v = z3[(size_t)r * 128 + c];
        s3 += v; q3 += v * v;
    }
    atomicAdd(&g_stats[5 * 128 + c], s3);
    atomicAdd(&g_stats[6 * 128 + c], q3);
}

// ---------------- finalize: beta softmax + BN affine params ----------------
__global__ void finalize_kernel(const float* __restrict__ gamma, const float* __restrict__ betaBN,
                                int MP, int MA) {
    int j = threadIdx.x;
    float w1 = g_wsum[0] / (float)MP;
    float w2 = g_wsum[1] / (float)MP;
    float m = fmaxf(w1, w2);
    float e1 = expf(w1 - m), e2 = expf(w2 - m);
    float b1 = e1 / (e1 + e2), b2 = e2 / (e1 + e2);
    if (j == 0) { g_beta[0] = b1; g_beta[1] = b2; }

    float S1 = g_stats[0 * 128 + j], S2 = g_stats[1 * 128 + j];
    float Q1 = g_stats[2 * 128 + j], Q2 = g_stats[3 * 128 + j];
    float CX = g_stats[4 * 128 + j];
    float S3 = g_stats[5 * 128 + j], Q3 = g_stats[6 * 128 + j];

    float invMP = 1.0f / (float)MP;
    float mu = (b1 * S1 + b2 * S2) * invMP;
    float ex2 = (b1 * b1 * Q1 + 2.f * b1 * b2 * CX + b2 * b2 * Q2) * invMP;
    float var = ex2 - mu * mu;
    float sc = gamma[j] * rsqrtf(var + 1e-5f);
    g_scale_p[j] = sc;
    g_shift_p[j] = betaBN[j] - mu * sc;

    float invMA = 1.0f / (float)MA;
    float mua = S3 * invMA;
    float vara = Q3 * invMA - mua * mua;
    float sca = gamma[j] * rsqrtf(vara + 1e-5f);
    g_scale_a[j] = sca;
    g_shift_a[j] = betaBN[j] - mua * sca;
}

// ---------------- combine + BN + row L2 normalize ----------------
__global__ __launch_bounds__(256) void out_paper_kernel(
    const float* __restrict__ z1, const float* __restrict__ z2,
    float* __restrict__ out, int M) {
    int gt = blockIdx.x * blockDim.x + threadIdx.x;
    int row = gt >> 5, lane = gt & 31;
    if (row >= M) return;
    float b1 = g_beta[0], b2 = g_beta[1];
    float4 v1 = *((const float4*)(z1 + (size_t)row * 128) + lane);
    float4 v2 = *((const float4*)(z2 + (size_t)row * 128) + lane);
    float4 sc = *(const float4*)&g_scale_p[lane * 4];
    float4 sh = *(const float4*)&g_shift_p[lane * 4];
    float4 y;
    y.x = (b1 * v1.x + b2 * v2.x) * sc.x + sh.x;
    y.y = (b1 * v1.y + b2 * v2.y) * sc.y + sh.y;
    y.z = (b1 * v1.z + b2 * v2.z) * sc.z + sh.z;
    y.w = (b1 * v1.w + b2 * v2.w) * sc.w + sh.w;
    float ss = y.x * y.x + y.y * y.y + y.z * y.z + y.w * y.w;
#pragma unroll
    for (int o = 16; o > 0; o >>= 1) ss += __shfl_xor_sync(0xffffffffu, ss, o);
    float inv = rsqrtf(ss + 1e-12f);
    float4 o4 = make_float4(y.x * inv, y.y * inv, y.z * inv, y.w * inv);
    *((float4*)(out + (size_t)row * 128) + lane) = o4;
}

__global__ __launch_bounds__(256) void out_author_kernel(
    const float* __restrict__ z3, float* __restrict__ out, int M) {
    int gt = blockIdx.x * blockDim.x + threadIdx.x;
    int row = gt >> 5, lane = gt & 31;
    if (row >= M) return;
    float4 v = *((const float4*)(z3 + (size_t)row * 128) + lane);
    float4 sc = *(const float4*)&g_scale_a[lane * 4];
    float4 sh = *(const float4*)&g_shift_a[lane * 4];
    float4 y;
    y.x = v.x * sc.x + sh.x;
    y.y = v.y * sc.y + sh.y;
    y.z = v.z * sc.z + sh.z;
    y.w = v.w * sc.w + sh.w;
    float ss = y.x * y.x + y.y * y.y + y.z * y.z + y.w * y.w;
#pragma unroll
    for (int o = 16; o > 0; o >>= 1) ss += __shfl_xor_sync(0xffffffffu, ss, o);
    float inv = rsqrtf(ss + 1e-12f);
    float4 o4 = make_float4(y.x * inv, y.y * inv, y.z * inv, y.w * inv);
    *((float4*)(out + (size_t)row * 128) + lane) = o4;
}

// ---------------- launch ----------------
extern "C" void kernel_launch(void* const* d_in, const int* in_sizes, int n_in,
                              void* d_out, int out_size) {
    const float* h_paper  = (const float*)d_in[0];
    const float* h_author = (const float*)d_in[1];
    const float* W1   = (const float*)d_in[2];
    const float* W2   = (const float*)d_in[3];
    const float* W3   = (const float*)d_in[4];
    const float* attW = (const float*)d_in[5];
    const float* attb = (const float*)d_in[6];
    const float* attq = (const float*)d_in[7];
    const float* gamma  = (const float*)d_in[8];
    const float* betaBN = (const float*)d_in[9];
    const int* s1 = (const int*)d_in[10];
    const int* d1 = (const int*)d_in[11];
    const int* s2 = (const int*)d_in[12];
    const int* d2 = (const int*)d_in[13];
    const int* s3 = (const int*)d_in[14];
    const int* d3 = (const int*)d_in[15];
    float* out = (float*)d_out;

    const int MP = in_sizes[0] / Dv;
    const int MA = in_sizes[1] / Dv;
    const int E  = in_sizes[10];

    float *agg1, *agg2, *agg3, *z1, *z2, *z3, *deg, *wsum;
    cudaGetSymbolAddress((void**)&agg1, g_agg1);
    cudaGetSymbolAddress((void**)&agg2, g_agg2);
    cudaGetSymbolAddress((void**)&agg3, g_agg3);
    cudaGetSymbolAddress((void**)&z1, g_z1);
    cudaGetSymbolAddress((void**)&z2, g_z2);
    cudaGetSymbolAddress((void**)&z3, g_z3);
    cudaGetSymbolAddress((void**)&deg, g_deg);
    cudaGetSymbolAddress((void**)&wsum, g_wsum);

    {
        size_t n = (size_t)MP * Dv;
        int blocks = (int)((n + 255) / 256);
        zero_kernel<<<blocks, 256>>>();
    }
    degree_kernel<<<(E + 255) / 256, 256>>>(s1, d1, s2, d2, s3, d3, E);
    rsqrt_deg_kernel<<<(6 * 50000 + 255) / 256, 256>>>(6 * 50000);

    {
        int warps = (E + 3) / 4;
        int blocks = (warps * 32 + 255) / 256;
        scatter_kernel<<<blocks, 256>>>(h_author, s1, d1, deg + 0 * 50000, agg1, E);
        scatter_kernel<<<blocks, 256>>>(h_paper,  s2, d2, deg + 2 * 50000, agg2, E);
        scatter_kernel<<<blocks, 256>>>(h_author, s3, d3, deg + 4 * 50000, agg3, E);
    }

    {
        dim3 gP((MP + 127) / 128, 2), gA((MA + 127) / 128, 2);
        gemm_tf32<0><<<gP, 256>>>(agg1, W1, deg + 1 * 50000, z1, nullptr, nullptr, nullptr, MP);
        gemm_tf32<0><<<gP, 256>>>(agg2, W2, deg + 3 * 50000, z2, nullptr, nullptr, nullptr, MP);
        gemm_tf32<0><<<gA, 256>>>(agg3, W3, deg + 5 * 50000, z3, nullptr, nullptr, nullptr, MA);

        gemm_tf32<1><<<gP, 256>>>(z1, attW, nullptr, nullptr, attb, attq, wsum + 0, MP);
        gemm_tf32<1><<<gP, 256>>>(z2, attW, nullptr, nullptr, attb, attq, wsum + 1, MP);
    }

    stats_paper_kernel<<<(MP + 255) / 256, 128>>>(z1, z2, MP);
    stats_author_kernel<<<(MA + 255) / 256, 128>>>(z3, MA);

    finalize_kernel<<<1, 128>>>(gamma, betaBN, MP, MA);

    out_paper_kernel<<<(MP * 32 + 255) / 256, 256>>>(z1, z2, out, MP);
    out_author_kernel<<<(MA * 32 + 255) / 256, 256>>>(z3, out + (size_t)MP * Dv, MA);
}

// round 5
// speedup vs baseline: 1.7212x; 1.1420x over previous
#include <cuda_runtime.h>
#include <cstdint>

#define NPv 50000
#define NAv 50000
#define Dv  128

// ---------------- scratch ----------------
__device__ float g_agg1[(size_t)NPv * Dv];
__device__ float g_agg2[(size_t)NPv * Dv];
__device__ float g_agg3[(size_t)NAv * Dv];
__device__ float g_z1[(size_t)NPv * Dv];
__device__ float g_z2[(size_t)NPv * Dv];
__device__ float g_z3[(size_t)NAv * Dv];
__device__ float g_deg[6 * 50000];
__device__ float g_stats[7 * 128];
__device__ float g_wsum[2];
__device__ float g_beta[2];
__device__ float g_scale_p[128], g_shift_p[128];
__device__ float g_scale_a[128], g_shift_a[128];

// ---------------- tf32 helpers ----------------
__device__ __forceinline__ uint32_t cvt_tf32(float x) {
    uint32_t r;
    asm("cvt.rna.tf32.f32 %0, %1;" : "=r"(r) : "f"(x));
    return r;
}
__device__ __forceinline__ void mma_tf32(float4& d, const uint32_t a[4],
                                         uint32_t b0, uint32_t b1) {
    asm volatile(
        "mma.sync.aligned.m16n8k8.row.col.f32.tf32.tf32.f32 "
        "{%0,%1,%2,%3},{%4,%5,%6,%7},{%8,%9},{%0,%1,%2,%3};"
        : "+f"(d.x), "+f"(d.y), "+f"(d.z), "+f"(d.w)
        : "r"(a[0]), "r"(a[1]), "r"(a[2]), "r"(a[3]), "r"(b0), "r"(b1));
}

// ---------------- zero scratch (vectorized) ----------------
__global__ void zero_kernel() {
    size_t i = (size_t)blockIdx.x * blockDim.x + threadIdx.x;   // float4 index
    size_t n4 = (size_t)NPv * Dv / 4;
    float4 z = make_float4(0.f, 0.f, 0.f, 0.f);
    if (i < n4) {
        ((float4*)g_agg1)[i] = z;
        ((float4*)g_agg2)[i] = z;
        ((float4*)g_agg3)[i] = z;
    }
    if (i < (6 * 50000) / 4) ((float4*)g_deg)[i] = z;
    if (i < (7 * 128) / 4) ((float4*)g_stats)[i] = z;
    if (i < 2) g_wsum[i] = 0.f;
}

// ---------------- degrees ----------------
__global__ void degree_kernel(const int* __restrict__ s1, const int* __restrict__ d1,
                              const int* __restrict__ s2, const int* __restrict__ d2,
                              const int* __restrict__ s3, const int* __restrict__ d3,
                              int nE) {
    int i = blockIdx.x * blockDim.x + threadIdx.x;
    if (i >= nE) return;
    atomicAdd(&g_deg[0 * 50000 + s1[i]], 1.0f);
    atomicAdd(&g_deg[1 * 50000 + d1[i]], 1.0f);
    atomicAdd(&g_deg[2 * 50000 + s2[i]], 1.0f);
    atomicAdd(&g_deg[3 * 50000 + d2[i]], 1.0f);
    atomicAdd(&g_deg[4 * 50000 + s3[i]], 1.0f);
    atomicAdd(&g_deg[5 * 50000 + d3[i]], 1.0f);
}

__global__ void rsqrt_deg_kernel(int n) {
    int i = blockIdx.x * blockDim.x + threadIdx.x;
    if (i < n) g_deg[i] = rsqrtf(fmaxf(g_deg[i], 1.0f));
}

// ---------------- scatter: 4 edges per warp (at LTS cap) ----------------
__global__ __launch_bounds__(256) void scatter_kernel(
    const float* __restrict__ H, const int* __restrict__ src, const int* __restrict__ dst,
    const float* __restrict__ rs_out, float* __restrict__ agg, int nE) {
    int warp = (blockIdx.x * blockDim.x + threadIdx.x) >> 5;
    int lane = threadIdx.x & 31;
    int e0 = warp << 2;
    if (e0 >= nE) return;

    int s[4], d[4];
#pragma unroll
    for (int i = 0; i < 4; i++) {
        int e = min(e0 + i, nE - 1);
        s[i] = __ldg(src + e);
        d[i] = __ldg(dst + e);
    }
    float sc[4];
#pragma unroll
    for (int i = 0; i < 4; i++) sc[i] = __ldg(rs_out + s[i]);
    float4 v[4];
#pragma unroll
    for (int i = 0; i < 4; i++)
        v[i] = *((const float4*)(H + (size_t)s[i] * Dv) + lane);

    int n = min(4, nE - e0);
#pragma unroll
    for (int i = 0; i < 4; i++) {
        if (i < n) {
            float4 u = v[i];
            float c = sc[i];
            u.x *= c; u.y *= c; u.z *= c; u.w *= c;
            float* p = agg + (size_t)d[i] * Dv + lane * 4;
            asm volatile("red.global.add.v4.f32 [%0], {%1,%2,%3,%4};"
                         :: "l"(p), "f"(u.x), "f"(u.y), "f"(u.z), "f"(u.w) : "memory");
        }
    }
}

// ============ TF32 GEMM core: block tile 128x128, 8 warps (4m x 2n) ==========
// warp tile 32 rows x 64 cols. K=128 chunked by 32, register-prefetch pipeline.
// As stride 36 -> A-frag banks 4*grp+tig (bijective); Ws stride 136 -> 8*tig+grp.

#define GEMM_PROLOGUE()                                                        \
    __shared__ float As[128][36];                                              \
    __shared__ float Ws[32][136];                                              \
    const int tid = threadIdx.x;                                               \
    const int wid = tid >> 5, lane = tid & 31;                                 \
    const int grp = lane >> 2, tig = lane & 3;                                 \
    const int rowBase = blockIdx.x * 128;                                      \
    const int rowOff = (wid & 3) * 32;                                         \
    const int colOff = (wid >> 2) * 64;                                        \
    float4 acc[2][8];                                                          \
    _Pragma("unroll") for (int ms = 0; ms < 2; ms++)                           \
        _Pragma("unroll") for (int ns = 0; ns < 8; ns++)                       \
            acc[ms][ns] = make_float4(0.f, 0.f, 0.f, 0.f);

#define LOAD_CHUNK(kc)                                                         \
    _Pragma("unroll") for (int j = 0; j < 4; j++) {                            \
        int i = tid + 256 * j;                                                 \
        int r = i >> 3, c4 = (i & 7) << 2;                                     \
        int gr = min(rowBase + r, M - 1);                                      \
        aPre[j] = *(const float4*)(A + (size_t)gr * 128 + (kc) * 32 + c4);     \
        int k = i >> 5, w4 = (i & 31) << 2;                                    \
        wPre[j] = *(const float4*)(W + (size_t)((kc) * 32 + k) * 128 + w4);    \
    }

#define STORE_CHUNK()                                                          \
    _Pragma("unroll") for (int j = 0; j < 4; j++) {                            \
        int i = tid + 256 * j;                                                 \
        int r = i >> 3, c4 = (i & 7) << 2;                                     \
        uint4 ta;                                                              \
        ta.x = cvt_tf32(aPre[j].x); ta.y = cvt_tf32(aPre[j].y);                \
        ta.z = cvt_tf32(aPre[j].z); ta.w = cvt_tf32(aPre[j].w);                \
        *(uint4*)&As[r][c4] = ta;                                              \
        int k = i >> 5, w4 = (i & 31) << 2;                                    \
        uint4 tw;                                                              \
        tw.x = cvt_tf32(wPre[j].x); tw.y = cvt_tf32(wPre[j].y);                \
        tw.z = cvt_tf32(wPre[j].z); tw.w = cvt_tf32(wPre[j].w);                \
        *(uint4*)&Ws[k][w4] = tw;                                              \
    }

#define MMA_CHUNK()                                                            \
    _Pragma("unroll") for (int ks = 0; ks < 4; ks++) {                         \
        int k0 = ks * 8;                                                       \
        uint32_t a[2][4];                                                      \
        _Pragma("unroll") for (int ms = 0; ms < 2; ms++) {                     \
            int r = rowOff + ms * 16 + grp;                                    \
            a[ms][0] = __float_as_uint(As[r][k0 + tig]);                       \
            a[ms][1] = __float_as_uint(As[r + 8][k0 + tig]);                   \
            a[ms][2] = __float_as_uint(As[r][k0 + tig + 4]);                   \
            a[ms][3] = __float_as_uint(As[r + 8][k0 + tig + 4]);               \
        }                                                                      \
        _Pragma("unroll") for (int ns = 0; ns < 8; ns++) {                     \
            int cn = colOff + ns * 8 + grp;                                    \
            uint32_t b0 = __float_as_uint(Ws[k0 + tig][cn]);                   \
            uint32_t b1 = __float_as_uint(Ws[k0 + tig + 4][cn]);               \
            mma_tf32(acc[0][ns], a[0], b0, b1);                                \
            mma_tf32(acc[1][ns], a[1], b0, b1);                                \
        }                                                                      \
    }

#define GEMM_MAINLOOP()                                                        \
    float4 aPre[4], wPre[4];                                                   \
    LOAD_CHUNK(0)                                                              \
    _Pragma("unroll") for (int kc = 0; kc < 4; kc++) {                         \
        if (kc > 0) __syncthreads();                                           \
        STORE_CHUNK()                                                          \
        __syncthreads();                                                       \
        if (kc < 3) { LOAD_CHUNK(kc + 1) }                                     \
        MMA_CHUNK()                                                            \
    }

// conv GEMM: C = (A @ W) * rs[row]; blockIdx.y selects relation
__global__ __launch_bounds__(256, 2) void conv_gemm_tf32(
    const float* __restrict__ A1, const float* __restrict__ A2, const float* __restrict__ A3,
    const float* __restrict__ W1, const float* __restrict__ W2, const float* __restrict__ W3,
    const float* __restrict__ rs1, const float* __restrict__ rs2, const float* __restrict__ rs3,
    float* __restrict__ C1, float* __restrict__ C2, float* __restrict__ C3, int M) {
    const int rel = blockIdx.y;
    const float* A = rel == 0 ? A1 : rel == 1 ? A2 : A3;
    const float* W = rel == 0 ? W1 : rel == 1 ? W2 : W3;
    const float* rs = rel == 0 ? rs1 : rel == 1 ? rs2 : rs3;
    float* C = rel == 0 ? C1 : rel == 1 ? C2 : C3;

    GEMM_PROLOGUE()
    GEMM_MAINLOOP()

#pragma unroll
    for (int ms = 0; ms < 2; ms++) {
        int rA = rowBase + rowOff + ms * 16 + grp;
        int rB = rA + 8;
        float sA = (rA < M) ? rs[rA] : 0.f;
        float sB = (rB < M) ? rs[rB] : 0.f;
#pragma unroll
        for (int ns = 0; ns < 8; ns++) {
            int cC = colOff + ns * 8 + 2 * tig;
            if (rA < M) {
                float2 o = make_float2(acc[ms][ns].x * sA, acc[ms][ns].y * sA);
                *(float2*)(C + (size_t)rA * 128 + cC) = o;
            }
            if (rB < M) {
                float2 o = make_float2(acc[ms][ns].z * sB, acc[ms][ns].w * sB);
                *(float2*)(C + (size_t)rB * 128 + cC) = o;
            }
        }
    }
}

// attention GEMM: wsum[y] += sum_rows tanh(Z@attW + b) . q; blockIdx.y selects Z
__global__ __launch_bounds__(256, 2) void att_gemm_tf32(
    const float* __restrict__ Z1, const float* __restrict__ Z2,
    const float* __restrict__ W,
    const float* __restrict__ bb, const float* __restrict__ qq,
    float* __restrict__ wsum, int M) {
    const float* A = blockIdx.y == 0 ? Z1 : Z2;

    GEMM_PROLOGUE()
    GEMM_MAINLOOP()

    float p = 0.f;
#pragma unroll
    for (int ms = 0; ms < 2; ms++) {
        int rA = rowBase + rowOff + ms * 16 + grp;
        int rB = rA + 8;
#pragma unroll
        for (int ns = 0; ns < 8; ns++) {
            int cC = colOff + ns * 8 + 2 * tig;
            float b0v = __ldg(bb + cC), b1v = __ldg(bb + cC + 1);
            float q0v = __ldg(qq + cC), q1v = __ldg(qq + cC + 1);
            if (rA < M)
                p += tanhf(acc[ms][ns].x + b0v) * q0v + tanhf(acc[ms][ns].y + b1v) * q1v;
            if (rB < M)
                p += tanhf(acc[ms][ns].z + b0v) * q0v + tanhf(acc[ms][ns].w + b1v) * q1v;
        }
    }
#pragma unroll
    for (int o = 16; o > 0; o >>= 1) p += __shfl_xor_sync(0xffffffffu, p, o);
    if (lane == 0) atomicAdd(wsum + blockIdx.y, p);
}

// ---------------- column moments ----------------
__global__ __launch_bounds__(128) void stats_paper_kernel(
    const float* __restrict__ z1, const float* __restrict__ z2, int M) {
    int c = threadIdx.x;
    int r0 = blockIdx.x * 128;
    int r1 = min(r0 + 128, M);
    float s1 = 0.f, s2 = 0.f, q1 = 0.f, q2 = 0.f, cx = 0.f;
    for (int r = r0; r < r1; r++) {
        float v1 = z1[(size_t)r * 128 + c];
        float v2 = z2[(size_t)r * 128 + c];
        s1 += v1; s2 += v2; q1 += v1 * v1; q2 += v2 * v2; cx += v1 * v2;
    }
    atomicAdd(&g_stats[0 * 128 + c], s1);
    atomicAdd(&g_stats[1 * 128 + c], s2);
    atomicAdd(&g_stats[2 * 128 + c], q1);
    atomicAdd(&g_stats[3 * 128 + c], q2);
    atomicAdd(&g_stats[4 * 128 + c], cx);
}

__global__ __launch_bounds__(128) void stats_author_kernel(const float* __restrict__ z3, int M) {
    int c = threadIdx.x;
    int r0 = blockIdx.x * 128;
    int r1 = min(r0 + 128, M);
    float s3 = 0.f, q3 = 0.f;
    for (int r = r0; r < r1; r++) {
        float v = z3[(size_t)r * 128 + c];
        s3 += v; q3 += v * v;
    }
    atomicAdd(&g_stats[5 * 128 + c], s3);
    atomicAdd(&g_stats[6 * 128 + c], q3);
}

// ---------------- finalize ----------------
__global__ void finalize_kernel(const float* __restrict__ gamma, const float* __restrict__ betaBN,
                                int MP, int MA) {
    int j = threadIdx.x;
    float w1 = g_wsum[0] / (float)MP;
    float w2 = g_wsum[1] / (float)MP;
    float m = fmaxf(w1, w2);
    float e1 = expf(w1 - m), e2 = expf(w2 - m);
    float b1 = e1 / (e1 + e2), b2 = e2 / (e1 + e2);
    if (j == 0) { g_beta[0] = b1; g_beta[1] = b2; }

    float S1 = g_stats[0 * 128 + j], S2 = g_stats[1 * 128 + j];
    float Q1 = g_stats[2 * 128 + j], Q2 = g_stats[3 * 128 + j];
    float CX = g_stats[4 * 128 + j];
    float S3 = g_stats[5 * 128 + j], Q3 = g_stats[6 * 128 + j];

    float invMP = 1.0f / (float)MP;
    float mu = (b1 * S1 + b2 * S2) * invMP;
    float ex2 = (b1 * b1 * Q1 + 2.f * b1 * b2 * CX + b2 * b2 * Q2) * invMP;
    float var = ex2 - mu * mu;
    float sc = gamma[j] * rsqrtf(var + 1e-5f);
    g_scale_p[j] = sc;
    g_shift_p[j] = betaBN[j] - mu * sc;

    float invMA = 1.0f / (float)MA;
    float mua = S3 * invMA;
    float vara = Q3 * invMA - mua * mua;
    float sca = gamma[j] * rsqrtf(vara + 1e-5f);
    g_scale_a[j] = sca;
    g_shift_a[j] = betaBN[j] - mua * sca;
}

// ---------------- combine + BN + row L2 normalize ----------------
__global__ __launch_bounds__(256) void out_paper_kernel(
    const float* __restrict__ z1, const float* __restrict__ z2,
    float* __restrict__ out, int M) {
    int gt = blockIdx.x * blockDim.x + threadIdx.x;
    int row = gt >> 5, lane = gt & 31;
    if (row >= M) return;
    float b1 = g_beta[0], b2 = g_beta[1];
    float4 v1 = *((const float4*)(z1 + (size_t)row * 128) + lane);
    float4 v2 = *((const float4*)(z2 + (size_t)row * 128) + lane);
    float4 sc = *(const float4*)&g_scale_p[lane * 4];
    float4 sh = *(const float4*)&g_shift_p[lane * 4];
    float4 y;
    y.x = (b1 * v1.x + b2 * v2.x) * sc.x + sh.x;
    y.y = (b1 * v1.y + b2 * v2.y) * sc.y + sh.y;
    y.z = (b1 * v1.z + b2 * v2.z) * sc.z + sh.z;
    y.w = (b1 * v1.w + b2 * v2.w) * sc.w + sh.w;
    float ss = y.x * y.x + y.y * y.y + y.z * y.z + y.w * y.w;
#pragma unroll
    for (int o = 16; o > 0; o >>= 1) ss += __shfl_xor_sync(0xffffffffu, ss, o);
    float inv = rsqrtf(ss + 1e-12f);
    float4 o4 = make_float4(y.x * inv, y.y * inv, y.z * inv, y.w * inv);
    *((float4*)(out + (size_t)row * 128) + lane) = o4;
}

__global__ __launch_bounds__(256) void out_author_kernel(
    const float* __restrict__ z3, float* __restrict__ out, int M) {
    int gt = blockIdx.x * blockDim.x + threadIdx.x;
    int row = gt >> 5, lane = gt & 31;
    if (row >= M) return;
    float4 v = *((const float4*)(z3 + (size_t)row * 128) + lane);
    float4 sc = *(const float4*)&g_scale_a[lane * 4];
    float4 sh = *(const float4*)&g_shift_a[lane * 4];
    float4 y;
    y.x = v.x * sc.x + sh.x;
    y.y = v.y * sc.y + sh.y;
    y.z = v.z * sc.z + sh.z;
    y.w = v.w * sc.w + sh.w;
    float ss = y.x * y.x + y.y * y.y + y.z * y.z + y.w * y.w;
#pragma unroll
    for (int o = 16; o > 0; o >>= 1) ss += __shfl_xor_sync(0xffffffffu, ss, o);
    float inv = rsqrtf(ss + 1e-12f);
    float4 o4 = make_float4(y.x * inv, y.y * inv, y.z * inv, y.w * inv);
    *((float4*)(out + (size_t)row * 128) + lane) = o4;
}

// ---------------- launch ----------------
extern "C" void kernel_launch(void* const* d_in, const int* in_sizes, int n_in,
                              void* d_out, int out_size) {
    const float* h_paper  = (const float*)d_in[0];
    const float* h_author = (const float*)d_in[1];
    const float* W1   = (const float*)d_in[2];
    const float* W2   = (const float*)d_in[3];
    const float* W3   = (const float*)d_in[4];
    const float* attW = (const float*)d_in[5];
    const float* attb = (const float*)d_in[6];
    const float* attq = (const float*)d_in[7];
    const float* gamma  = (const float*)d_in[8];
    const float* betaBN = (const float*)d_in[9];
    const int* s1 = (const int*)d_in[10];
    const int* d1 = (const int*)d_in[11];
    const int* s2 = (const int*)d_in[12];
    const int* d2 = (const int*)d_in[13];
    const int* s3 = (const int*)d_in[14];
    const int* d3 = (const int*)d_in[15];
    float* out = (float*)d_out;

    const int MP = in_sizes[0] / Dv;
    const int MA = in_sizes[1] / Dv;
    const int E  = in_sizes[10];

    float *agg1, *agg2, *agg3, *z1, *z2, *z3, *deg, *wsum;
    cudaGetSymbolAddress((void**)&agg1, g_agg1);
    cudaGetSymbolAddress((void**)&agg2, g_agg2);
    cudaGetSymbolAddress((void**)&agg3, g_agg3);
    cudaGetSymbolAddress((void**)&z1, g_z1);
    cudaGetSymbolAddress((void**)&z2, g_z2);
    cudaGetSymbolAddress((void**)&z3, g_z3);
    cudaGetSymbolAddress((void**)&deg, g_deg);
    cudaGetSymbolAddress((void**)&wsum, g_wsum);

    {
        size_t n4 = (size_t)MP * Dv / 4;
        int blocks = (int)((n4 + 255) / 256);
        zero_kernel<<<blocks, 256>>>();
    }
    degree_kernel<<<(E + 255) / 256, 256>>>(s1, d1, s2, d2, s3, d3, E);
    rsqrt_deg_kernel<<<(6 * 50000 + 255) / 256, 256>>>(6 * 50000);

    {
        int warps = (E + 3) / 4;
        int blocks = (warps * 32 + 255) / 256;
        scatter_kernel<<<blocks, 256>>>(h_author, s1, d1, deg + 0 * 50000, agg1, E);
        scatter_kernel<<<blocks, 256>>>(h_paper,  s2, d2, deg + 2 * 50000, agg2, E);
        scatter_kernel<<<blocks, 256>>>(h_author, s3, d3, deg + 4 * 50000, agg3, E);
    }

    {
        dim3 g((MP + 127) / 128, 3);
        conv_gemm_tf32<<<g, 256>>>(agg1, agg2, agg3, W1, W2, W3,
                                   deg + 1 * 50000, deg + 3 * 50000, deg + 5 * 50000,
                                   z1, z2, z3, MP);
        dim3 ga((MP + 127) / 128, 2);
        att_gemm_tf32<<<ga, 256>>>(z1, z2, attW, attb, attq, wsum, MP);
    }

    stats_paper_kernel<<<(MP + 127) / 128, 128>>>(z1, z2, MP);
    stats_author_kernel<<<(MA + 127) / 128, 128>>>(z3, MA);

    finalize_kernel<<<1, 128>>>(gamma, betaBN, MP, MA);

    out_paper_kernel<<<(MP * 32 + 255) / 256, 256>>>(z1, z2, out, MP);
    out_author_kernel<<<(MA * 32 + 255) / 256, 256>>>(z3, out + (size_t)MP * Dv, MA);
}